// round 11
// baseline (speedup 1.0000x reference)
#include <cuda_runtime.h>
#include <cstdint>

#define NUM_ROWS 1000000
#define DIM 128
#define KPROBES 8

// Persistent-grid variant of the R5 winner: same per-token code (1 token
// per warp-iteration, MLP=8 front-batched LDG.128 via __ldcg), but a fixed
// grid of 148 SMs x 8 blocks with a grid-stride loop instead of 8192
// one-shot blocks. Goal: eliminate ~6 wave transitions where the SM's
// in-flight-miss population collapses and must be rebuilt.
__global__ __launch_bounds__(256) void bloom_embed_kernel(
    const void* __restrict__ t_raw,
    const float* __restrict__ W,
    float* __restrict__ out,
    int n_tokens,
    int n_warps_total)
{
    int warp0 = (blockIdx.x * blockDim.x + threadIdx.x) >> 5;
    int lane  = threadIdx.x & 31;

    // --- inline dtype detection (int64 vs int32 token storage) ---
    // Tokens are uniform in [0, 1e9). If stored int64, the high 32 bits of
    // every 8-byte word are zero; if int32, a high half is another random
    // token (zero w.p. ~1e-9). 4 words checked across the warp.
    unsigned long long probe =
        ((const unsigned long long*)t_raw)[lane & 3];
    unsigned ball = __ballot_sync(0xffffffffu, (probe >> 32) == 0ULL);
    bool t_is_i64 = (ball == 0xffffffffu);

    const int col = lane * 4;

    for (int gwarp = warp0; gwarp < n_tokens; gwarp += n_warps_total) {
        // --- load token ---
        long long tok;
        if (t_is_i64)
            tok = __ldcg(((const long long*)t_raw) + gwarp);
        else
            tok = (long long)__ldcg(((const int*)t_raw) + gwarp);

        // --- hash: lanes 0..7 (replicated x4) each compute one probe ---
        long long h = tok + (long long)(lane & 7);
        // Mueller hash, int64 wrapping semantics (arith shift, wrap-mul).
        h = (long long)(((unsigned long long)((h >> 16) ^ h)) * 73244475ULL);
        h = (long long)(((unsigned long long)((h >> 16) ^ h)) * 73244475ULL);
        h = (h >> 16) ^ h;
        long long m = h % (long long)NUM_ROWS;
        if (m < 0) m += NUM_ROWS;        // Python/jnp mod: sign of divisor
        int idx = (int)m;

        // broadcast the 8 probe indices to all lanes
        int rid[KPROBES];
#pragma unroll
        for (int k = 0; k < KPROBES; k++)
            rid[k] = __shfl_sync(0xffffffffu, idx, k);

        // --- front-batched gather: 8 independent LDG.128 (MLP=8) ---
        float4 v[KPROBES];
#pragma unroll
        for (int k = 0; k < KPROBES; k++)
            v[k] = __ldcg(reinterpret_cast<const float4*>(
                       W + (size_t)rid[k] * DIM + col));

        float4 acc = v[0];
#pragma unroll
        for (int k = 1; k < KPROBES; k++) {
            acc.x += v[k].x; acc.y += v[k].y;
            acc.z += v[k].z; acc.w += v[k].w;
        }
        const float s = 1.0f / (float)KPROBES;
        acc.x *= s; acc.y *= s; acc.z *= s; acc.w *= s;

        *reinterpret_cast<float4*>(out + (size_t)gwarp * DIM + col) = acc;
    }
}

extern "C" void kernel_launch(void* const* d_in, const int* in_sizes, int n_in,
                              void* d_out, int out_size)
{
    // Robust input selection: t is the small tensor (65,536 elements),
    // W is the big one (128,000,000 elements), regardless of metadata order.
    int ti = 0, wi = 1;
    if (n_in >= 2 && in_sizes[0] > in_sizes[1]) { ti = 1; wi = 0; }

    const void*  t = d_in[ti];
    const float* W = (const float*)d_in[wi];
    float*     out = (float*)d_out;

    int n_tokens = in_sizes[ti];                     // 65536

    // Persistent grid: 8 blocks per SM x 148 SMs (GB300 has 152; 148-152
    // both fine — grid-stride handles any count), 8 warps per block.
    int threads = 256;
    int blocks  = 148 * 8;                           // 1184 blocks, 1 wave
    int n_warps_total = blocks * (threads / 32);     // 9472 warps
    bloom_embed_kernel<<<blocks, threads>>>(t, W, out, n_tokens, n_warps_total);
}

// round 12
// speedup vs baseline: 1.0735x; 1.0735x over previous
#include <cuda_runtime.h>
#include <cstdint>

#define NUM_ROWS 1000000
#define DIM 128
#define KPROBES 8

// FINAL KERNEL (R5 configuration).
//
// BloomEmbed is a uniform-random hashed-embedding gather: 65,536 tokens x
// 8 Mueller-hash probes into a 512 MB fp32 table, averaged. Mandatory
// traffic ~241 MB (209 MB unique rows + 32 MB writes); this kernel moves
// ~258 MB at 5.8-5.9 TB/s => ~93% traffic-optimal, pinned at the ~74%
// DRAM-active ceiling for random 512B-granule access.
//
// Exhaustively probed (R2-R11): single launch (WIN), __ldcg L1-bypass on
// gathers (WIN), streaming stores (neutral), MLP=16 via 2 tok/warp (loss),
// 512-thread blocks (loss), persistent grid (neutral). Identical-source
// noise band: +/-0.7 us. The request stream's randomness is defined by the
// hash; no kernel-side lever changes the binding DRAM bank-efficiency
// constraint.
__global__ __launch_bounds__(256) void bloom_embed_kernel(
    const void* __restrict__ t_raw,
    const float* __restrict__ W,
    float* __restrict__ out,
    int n_tokens)
{
    int gwarp = (blockIdx.x * blockDim.x + threadIdx.x) >> 5;
    int lane  = threadIdx.x & 31;
    if (gwarp >= n_tokens) return;

    // --- inline dtype detection (int64 vs int32 token storage) ---
    // Tokens are uniform in [0, 1e9). If stored int64, the high 32 bits of
    // every 8-byte word are zero. If stored int32, each 8-byte word's high
    // half is another random token (zero w.p. ~1e-9). Lanes check the first
    // 4 words (lane & 3); all-hi-zero across the warp => int64.
    unsigned long long probe =
        ((const unsigned long long*)t_raw)[lane & 3];
    unsigned ball = __ballot_sync(0xffffffffu, (probe >> 32) == 0ULL);
    bool t_is_i64 = (ball == 0xffffffffu);

    // --- load token ---
    long long tok;
    if (t_is_i64)
        tok = ((const long long*)t_raw)[gwarp];
    else
        tok = (long long)((const int*)t_raw)[gwarp];

    // --- hash: lanes 0..7 (replicated x4) each compute one probe ---
    long long h = tok + (long long)(lane & 7);
    // Mueller hash with int64 wrapping semantics (arith shift, wrap-mul).
    h = (long long)(((unsigned long long)((h >> 16) ^ h)) * 73244475ULL);
    h = (long long)(((unsigned long long)((h >> 16) ^ h)) * 73244475ULL);
    h = (h >> 16) ^ h;
    long long m = h % (long long)NUM_ROWS;
    if (m < 0) m += NUM_ROWS;            // Python/jnp mod: sign of divisor
    int idx = (int)m;

    // broadcast the 8 probe indices to all lanes
    int rid[KPROBES];
#pragma unroll
    for (int k = 0; k < KPROBES; k++)
        rid[k] = __shfl_sync(0xffffffffu, idx, k);

    // --- front-batched gather: 8 independent LDG.128 per lane (MLP=8) ---
    // __ldcg: L2-only caching. W rows are random within 512 MB -> L1 hit
    // rate ~0; skipping L1 allocation avoids useless fills/evictions and
    // L1tex wavefront overhead.
    const int col = lane * 4;
    float4 v[KPROBES];
#pragma unroll
    for (int k = 0; k < KPROBES; k++)
        v[k] = __ldcg(reinterpret_cast<const float4*>(
                   W + (size_t)rid[k] * DIM + col));

    float4 acc = v[0];
#pragma unroll
    for (int k = 1; k < KPROBES; k++) {
        acc.x += v[k].x; acc.y += v[k].y; acc.z += v[k].z; acc.w += v[k].w;
    }
    const float s = 1.0f / (float)KPROBES;
    acc.x *= s; acc.y *= s; acc.z *= s; acc.w *= s;

    *reinterpret_cast<float4*>(out + (size_t)gwarp * DIM + col) = acc;
}

extern "C" void kernel_launch(void* const* d_in, const int* in_sizes, int n_in,
                              void* d_out, int out_size)
{
    // Robust input selection: t is the small tensor (65,536 elements),
    // W is the big one (128,000,000 elements), regardless of metadata order.
    int ti = 0, wi = 1;
    if (n_in >= 2 && in_sizes[0] > in_sizes[1]) { ti = 1; wi = 0; }

    const void*  t = d_in[ti];
    const float* W = (const float*)d_in[wi];
    float*     out = (float*)d_out;

    int n_tokens = in_sizes[ti];                     // 65536

    int threads = 256;                               // 8 warps -> 8 tokens/block
    int blocks = (n_tokens * 32 + threads - 1) / threads;
    bloom_embed_kernel<<<blocks, threads>>>(t, W, out, n_tokens);
}